// round 14
// baseline (speedup 1.0000x reference)
#include <cuda_runtime.h>
#include <cuda_fp16.h>
#include <cstdint>

#define NN 256
#define NT 2048
#define NF 128

__device__ __half g_adj16[NN * NN];   // rownorm(adj+I), fp16, [m][k]

__device__ __forceinline__ uint32_t smem_u32(const void* p) {
    uint32_t a;
    asm("{ .reg .u64 t; cvta.to.shared.u64 t, %1; cvt.u32.u64 %0, t; }" : "=r"(a) : "l"(p));
    return a;
}
__device__ __forceinline__ uint32_t packh2(float x, float y) {
    __half2 h = __floats2half2_rn(x, y);
    return *reinterpret_cast<uint32_t*>(&h);
}
#define CP_ASYNC16(dst, src) \
    asm volatile("cp.async.cg.shared.global [%0], [%1], 16;" :: "r"(dst), "l"(src) : "memory")
#define CP_COMMIT() asm volatile("cp.async.commit_group;" ::: "memory")
#define CP_WAIT0()  asm volatile("cp.async.wait_group 0;" ::: "memory")

// ---------------------------------------------------------------------------
__global__ void prep_kernel(const float* __restrict__ adj) {
    __shared__ float red[256];
    int m = blockIdx.x, j = threadIdx.x;
    float v = adj[m * NN + j] + (j == m ? 1.0f : 0.0f);
    red[j] = v;
    __syncthreads();
#pragma unroll
    for (int off = 128; off > 0; off >>= 1) {
        if (j < off) red[j] += red[j + off];
        __syncthreads();
    }
    g_adj16[m * NN + j] = __float2half_rn(v / red[0]);
}

// ---------------------------------------------------------------------------
// Persistent fused GCN. grid = #SMs; each CTA loops t = bid, bid+grid, ...
// 256 threads = 8 warps (4m x 2n), warp tile 64x64, m16n8k16, fp32 accum.
//
// smem (224 KB dynamic):
//   ADJ [0,      131072): adj_hat fp16 resident, 256 rows x 512B, XOR swizzle
//                         (cp.async once, overlapped with first phase 1)
//   SW  [131072, 163840): W fp16 resident, 128 rows x 256B, XOR swizzle
//   SXW [163840, 229376): xw slab fp16, 256 rows x 256B, XOR swizzle
//                         phase-1 X staging (2 x 20480B) aliases this region
// ---------------------------------------------------------------------------
#define ADJ_OFF  0
#define SW_OFF   131072
#define SXW_OFF  163840
#define ASTAGE   20480
#define SMEM_TOT 229376

__global__ void __launch_bounds__(256, 1)
fused_gcn(const float* __restrict__ X, const float* __restrict__ W,
          float* __restrict__ out, const float* __restrict__ bias)
{
    extern __shared__ __align__(128) char smem[];
    const uint32_t base = smem_u32(smem);
    const uint32_t ADJ = base + ADJ_OFF;
    const uint32_t SW  = base + SW_OFF;
    const uint32_t SXW = base + SXW_OFF;
    const uint32_t STG = SXW;                  // phase-1 staging aliases SXW

    const int tid  = threadIdx.x;
    const int warp = tid >> 5;
    const int lane = tid & 31;
    const int lr   = lane & 15, lh = lane >> 4;
    const int grp  = lane >> 2, tg = lane & 3;
    const int warp_m = (warp & 3) * 64;
    const int warp_n = (warp >> 2) * 64;

    float acc[4][8][4];     // 128 regs
    float4 xr[4][2];        // phase-1 staging transients

    auto zero_acc = [&] {
#pragma unroll
        for (int i = 0; i < 4; i++)
#pragma unroll
            for (int j = 0; j < 8; j++)
#pragma unroll
                for (int r = 0; r < 4; r++) acc[i][j][r] = 0.0f;
    };
    auto sts16 = [](uint32_t addr, uint4 v) {
        asm volatile("st.shared.v4.b32 [%0], {%1,%2,%3,%4};"
                     :: "r"(addr), "r"(v.x), "r"(v.y), "r"(v.z), "r"(v.w) : "memory");
    };

    // ---- one-time prologue: adj -> ADJ (cp.async), W -> SW ----
#pragma unroll
    for (int i = 0; i < 32; i++) {
        int idx = tid + i * 256;               // 8192 x 16B
        int m = idx >> 5, u = idx & 31;
        CP_ASYNC16(ADJ + m * 512 + ((u * 16) ^ ((m & 7) << 4)),
                   g_adj16 + m * NN + u * 8);
    }
    CP_COMMIT();
#pragma unroll
    for (int p = 0; p < 8; p++) {
        int u = tid + p * 256;
        int row = u >> 4, seg = u & 15;
        const float4* src = (const float4*)(W + row * NF + seg * 8);
        float4 v0 = src[0], v1 = src[1];
        uint4 w;
        w.x = packh2(v0.x, v0.y); w.y = packh2(v0.z, v0.w);
        w.z = packh2(v1.x, v1.y); w.w = packh2(v1.z, v1.w);
        sts16(SW + row * 256 + ((seg * 16) ^ ((row & 7) << 4)), w);
    }
    zero_acc();

    // ---- phase-1 producers (reg path, fp32 -> fp16) ----
    auto loadX = [&](int t, int c) {
#pragma unroll
        for (int i = 0; i < 4; i++) {
            int u = tid + i * 256;
            int row = u >> 2, seg = u & 3;
            const float4* src = (const float4*)(X + ((size_t)row * NT + t) * NF + c * 32 + seg * 8);
            xr[i][0] = src[0];
            xr[i][1] = src[1];
        }
    };
    auto stsX = [&](int s) {
#pragma unroll
        for (int i = 0; i < 4; i++) {
            int u = tid + i * 256;
            int row = u >> 2, seg = u & 3;
            uint4 v;
            v.x = packh2(xr[i][0].x, xr[i][0].y); v.y = packh2(xr[i][0].z, xr[i][0].w);
            v.z = packh2(xr[i][1].x, xr[i][1].y); v.w = packh2(xr[i][1].z, xr[i][1].w);
            sts16(STG + s * ASTAGE + row * 80 + seg * 16, v);
        }
    };

    // phase-1 BK32 chunk: A from staging (80B rows), B = SW (256B rows, XOR)
    auto mma_p1 = [&](int c, int s) {
        const uint32_t ab = STG + s * ASTAGE;
#pragma unroll
        for (int kk = 0; kk < 2; kk++) {
            const int ke = kk * 16;
            uint32_t a[4][4];
#pragma unroll
            for (int fm = 0; fm < 4; fm++) {
                uint32_t ad = ab + (warp_m + fm * 16 + lr) * 80 + lh * 16 + ke * 2;
                asm volatile("ldmatrix.sync.aligned.m8n8.x4.shared.b16 {%0,%1,%2,%3}, [%4];"
                             : "=r"(a[fm][0]), "=r"(a[fm][1]), "=r"(a[fm][2]), "=r"(a[fm][3])
                             : "r"(ad));
            }
            uint32_t b[4][4];
#pragma unroll
            for (int np = 0; np < 4; np++) {
                int krw = c * 32 + ke + lr;
                uint32_t bn = (uint32_t)(warp_n + np * 16 + lh * 8) * 2;
                uint32_t bd = SW + krw * 256 + (bn ^ ((krw & 7) << 4));
                asm volatile("ldmatrix.sync.aligned.m8n8.x4.trans.shared.b16 {%0,%1,%2,%3}, [%4];"
                             : "=r"(b[np][0]), "=r"(b[np][1]), "=r"(b[np][2]), "=r"(b[np][3])
                             : "r"(bd));
            }
#pragma unroll
            for (int fm = 0; fm < 4; fm++)
#pragma unroll
                for (int fn = 0; fn < 8; fn++) {
                    const int np = fn >> 1, pr = fn & 1;
                    asm volatile(
                        "mma.sync.aligned.m16n8k16.row.col.f32.f16.f16.f32 "
                        "{%0,%1,%2,%3}, {%4,%5,%6,%7}, {%8,%9}, {%0,%1,%2,%3};"
                        : "+f"(acc[fm][fn][0]), "+f"(acc[fm][fn][1]),
                          "+f"(acc[fm][fn][2]), "+f"(acc[fm][fn][3])
                        : "r"(a[fm][0]), "r"(a[fm][1]), "r"(a[fm][2]), "r"(a[fm][3]),
                          "r"(b[np][pr * 2]), "r"(b[np][pr * 2 + 1]));
                }
        }
    };

    // phase-2 k16 step: A from resident ADJ (512B rows, XOR), B = SXW
    auto mma_p2 = [&](int st) {
        uint32_t a[4][4];
#pragma unroll
        for (int fm = 0; fm < 4; fm++) {
            int row = warp_m + fm * 16 + lr;
            uint32_t kbyte = (uint32_t)(st * 32 + lh * 16);
            uint32_t ad = ADJ + row * 512 + (kbyte ^ ((row & 7) << 4));
            asm volatile("ldmatrix.sync.aligned.m8n8.x4.shared.b16 {%0,%1,%2,%3}, [%4];"
                         : "=r"(a[fm][0]), "=r"(a[fm][1]), "=r"(a[fm][2]), "=r"(a[fm][3])
                         : "r"(ad));
        }
        uint32_t b[4][4];
#pragma unroll
        for (int np = 0; np < 4; np++) {
            int krw = st * 16 + lr;
            uint32_t bn = (uint32_t)(warp_n + np * 16 + lh * 8) * 2;
            uint32_t bd = SXW + krw * 256 + (bn ^ ((krw & 7) << 4));
            asm volatile("ldmatrix.sync.aligned.m8n8.x4.trans.shared.b16 {%0,%1,%2,%3}, [%4];"
                         : "=r"(b[np][0]), "=r"(b[np][1]), "=r"(b[np][2]), "=r"(b[np][3])
                         : "r"(bd));
        }
#pragma unroll
        for (int fm = 0; fm < 4; fm++)
#pragma unroll
            for (int fn = 0; fn < 8; fn++) {
                const int np = fn >> 1, pr = fn & 1;
                asm volatile(
                    "mma.sync.aligned.m16n8k16.row.col.f32.f16.f16.f32 "
                    "{%0,%1,%2,%3}, {%4,%5,%6,%7}, {%8,%9}, {%0,%1,%2,%3};"
                    : "+f"(acc[fm][fn][0]), "+f"(acc[fm][fn][1]),
                      "+f"(acc[fm][fn][2]), "+f"(acc[fm][fn][3])
                    : "r"(a[fm][0]), "r"(a[fm][1]), "r"(a[fm][2]), "r"(a[fm][3]),
                      "r"(b[np][pr * 2]), "r"(b[np][pr * 2 + 1]));
            }
    };

    // ---- persistent t loop ----
    for (int t = blockIdx.x; t < NT; t += gridDim.x) {
        // stage X chunk 0 (also: prev phase-2 SXW reads sealed by loop-end bar)
        loadX(t, 0);
        stsX(0);
        __syncthreads();

        // phase 1: xw = X_t @ W (4 chunks, double-buffered)
#pragma unroll
        for (int c = 0; c < 4; c++) {
            const int s = c & 1;
            if (c < 3) loadX(t, c + 1);
            mma_p1(c, s);
            if (c < 3) { stsX(s ^ 1); __syncthreads(); }
        }
        __syncthreads();               // seal staging reads

        // epilogue 1: acc -> SXW (fp16, XOR)
#pragma unroll
        for (int fm = 0; fm < 4; fm++) {
            const int r0 = warp_m + fm * 16 + grp;
#pragma unroll
            for (int fn = 0; fn < 8; fn++) {
                const int cb = (warp_n + fn * 8 + tg * 2) * 2;
                uint32_t h0 = packh2(acc[fm][fn][0], acc[fm][fn][1]);
                uint32_t h1 = packh2(acc[fm][fn][2], acc[fm][fn][3]);
                asm volatile("st.shared.b32 [%0], %1;"
                             :: "r"(SXW + r0 * 256 + (cb ^ ((r0 & 7) << 4))), "r"(h0) : "memory");
                asm volatile("st.shared.b32 [%0], %1;"
                             :: "r"(SXW + (r0 + 8) * 256 + (cb ^ (((r0 + 8) & 7) << 4))), "r"(h1) : "memory");
            }
        }
        zero_acc();
        CP_WAIT0();                    // adj resident (no-op after first t)
        __syncthreads();

        // phase 2: out_t = adj_hat @ xw + bias (16 k-steps, barrier-free)
#pragma unroll
        for (int st = 0; st < 16; st++) mma_p2(st);

        // epilogue 2
#pragma unroll
        for (int fm = 0; fm < 4; fm++) {
            const int r0 = warp_m + fm * 16 + grp;
#pragma unroll
            for (int fn = 0; fn < 8; fn++) {
                const int col = warp_n + fn * 8 + tg * 2;
                float2 b2 = *(const float2*)(bias + col);
                float2 v0 = { acc[fm][fn][0] + b2.x, acc[fm][fn][1] + b2.y };
                float2 v1 = { acc[fm][fn][2] + b2.x, acc[fm][fn][3] + b2.y };
                *(float2*)(out + ((size_t)r0 * NT + t) * NF + col)       = v0;
                *(float2*)(out + ((size_t)(r0 + 8) * NT + t) * NF + col) = v1;
            }
        }
        zero_acc();
        __syncthreads();               // seal phase-2 SXW reads before next stageX
    }
}

// ---------------------------------------------------------------------------
extern "C" void kernel_launch(void* const* d_in, const int* in_sizes, int n_in,
                              void* d_out, int out_size) {
    (void)in_sizes; (void)n_in; (void)out_size;
    const float* node_feats = (const float*)d_in[0];   // [256,2048,128]
    const float* adj        = (const float*)d_in[1];   // [256,256]
    const float* weight     = (const float*)d_in[2];   // [128,128]
    const float* bias       = (const float*)d_in[3];   // [128]
    float* out = (float*)d_out;

    cudaFuncSetAttribute(fused_gcn, cudaFuncAttributeMaxDynamicSharedMemorySize, SMEM_TOT);

    int sms = 0;
    cudaDeviceGetAttribute(&sms, cudaDevAttrMultiProcessorCount, 0);
    if (sms <= 0 || sms > 1024) sms = 152;

    prep_kernel<<<NN, 256>>>(adj);
    fused_gcn<<<sms, 256, SMEM_TOT>>>(node_feats, weight, out, bias);
}

// round 17
// speedup vs baseline: 1.0060x; 1.0060x over previous
#include <cuda_runtime.h>
#include <cuda_fp16.h>
#include <cstdint>

#define NN 256
#define NT 2048
#define NF 128

__device__ __half g_adj16[NN * NN];   // rownorm(adj+I), fp16, [m][k]

__device__ __forceinline__ uint32_t smem_u32(const void* p) {
    uint32_t a;
    asm("{ .reg .u64 t; cvta.to.shared.u64 t, %1; cvt.u32.u64 %0, t; }" : "=r"(a) : "l"(p));
    return a;
}
__device__ __forceinline__ uint32_t packh2(float x, float y) {
    __half2 h = __floats2half2_rn(x, y);
    return *reinterpret_cast<uint32_t*>(&h);
}

// ---------------------------------------------------------------------------
__global__ void prep_kernel(const float* __restrict__ adj) {
    __shared__ float red[256];
    int m = blockIdx.x, j = threadIdx.x;
    float v = adj[m * NN + j] + (j == m ? 1.0f : 0.0f);
    red[j] = v;
    __syncthreads();
#pragma unroll
    for (int off = 128; off > 0; off >>= 1) {
        if (j < off) red[j] += red[j + off];
        __syncthreads();
    }
    g_adj16[m * NN + j] = __float2half_rn(v / red[0]);
}

// ---------------------------------------------------------------------------
// Fused GCN, BK=64, 6 barriers/CTA. One CTA per t, 256 threads = 8 warps
// (4m x 2n), warp tile 64x64, m16n8k16, fp32 accum.
//
// smem (168 KB dynamic):
//   SW  [0,      32768): W fp16, 128 k-rows x 256B, XOR swizzle
//   SXW [32768,  98304): xw slab fp16, 256 rows x 256B, XOR swizzle
//   STG [98304, 172032): A staging, 2 stages x (256 rows x 144B)
//                        (BK64: 128B data + 16B pad; 4-bank shift per row)
// ---------------------------------------------------------------------------
#define SW_OFF   0
#define SXW_OFF  32768
#define STG_OFF  98304
#define ASTR     144
#define ASTAGE   36864
#define SMEM_TOT 172032

__global__ void __launch_bounds__(256, 1)
fused_gcn(const float* __restrict__ X, const float* __restrict__ W,
          float* __restrict__ out, const float* __restrict__ bias)
{
    extern __shared__ __align__(128) char smem[];
    const uint32_t base = smem_u32(smem);
    const uint32_t SW  = base + SW_OFF;
    const uint32_t SXW = base + SXW_OFF;
    const uint32_t STG = base + STG_OFF;

    const int t    = blockIdx.x;
    const int tid  = threadIdx.x;
    const int warp = tid >> 5;
    const int lane = tid & 31;
    const int lr   = lane & 15, lh = lane >> 4;
    const int grp  = lane >> 2, tg = lane & 3;
    const int warp_m = (warp & 3) * 64;
    const int warp_n = (warp >> 2) * 64;

    float acc[4][8][4];       // 128 regs
    float4 xr[4][2];          // X transients (one 4-unit wave)
    uint4  ar[4];             // adj transients (one 4-unit wave)

    auto zero_acc = [&] {
#pragma unroll
        for (int i = 0; i < 4; i++)
#pragma unroll
            for (int j = 0; j < 8; j++)
#pragma unroll
                for (int r = 0; r < 4; r++) acc[i][j][r] = 0.0f;
    };
    auto sts16 = [](uint32_t addr, uint4 v) {
        asm volatile("st.shared.v4.b32 [%0], {%1,%2,%3,%4};"
                     :: "r"(addr), "r"(v.x), "r"(v.y), "r"(v.z), "r"(v.w) : "memory");
    };

    // ---- producers: BK64 chunk = 2048 16B-units; 8/thread in 2 waves of 4 ----
    // unit u: row = u>>3 (0..255), seg = u&7 (16B each, 128B data per row)
    auto loadXw = [&](int c, int w) {
#pragma unroll
        for (int i = 0; i < 4; i++) {
            int u = tid + (w * 4 + i) * 256;
            int row = u >> 3, seg = u & 7;
            const float4* src = (const float4*)(X + ((size_t)row * NT + t) * NF + c * 64 + seg * 8);
            xr[i][0] = src[0];
            xr[i][1] = src[1];
        }
    };
    auto stsXw = [&](int s, int w) {
#pragma unroll
        for (int i = 0; i < 4; i++) {
            int u = tid + (w * 4 + i) * 256;
            int row = u >> 3, seg = u & 7;
            uint4 v;
            v.x = packh2(xr[i][0].x, xr[i][0].y); v.y = packh2(xr[i][0].z, xr[i][0].w);
            v.z = packh2(xr[i][1].x, xr[i][1].y); v.w = packh2(xr[i][1].z, xr[i][1].w);
            sts16(STG + s * ASTAGE + row * ASTR + seg * 16, v);
        }
    };
    auto loadAw = [&](int c, int w) {
#pragma unroll
        for (int i = 0; i < 4; i++) {
            int u = tid + (w * 4 + i) * 256;
            int row = u >> 3, seg = u & 7;
            ar[i] = *(const uint4*)(g_adj16 + row * NN + c * 64 + seg * 8);
        }
    };
    auto stsAw = [&](int s, int w) {
#pragma unroll
        for (int i = 0; i < 4; i++) {
            int u = tid + (w * 4 + i) * 256;
            int row = u >> 3, seg = u & 7;
            sts16(STG + s * ASTAGE + row * ASTR + seg * 16, ar[i]);
        }
    };

    // one k16 step: A from staging stage s (144B rows), B from Bbase (256B, XOR)
    auto mma_step = [&](int s, int kk, uint32_t Bbase, int kb) {
        const uint32_t ab = STG + s * ASTAGE;
        const int ke = kk * 16;
        uint32_t a[4][4];
#pragma unroll
        for (int fm = 0; fm < 4; fm++) {
            uint32_t ad = ab + (warp_m + fm * 16 + lr) * ASTR + lh * 16 + ke * 2;
            asm volatile("ldmatrix.sync.aligned.m8n8.x4.shared.b16 {%0,%1,%2,%3}, [%4];"
                         : "=r"(a[fm][0]), "=r"(a[fm][1]), "=r"(a[fm][2]), "=r"(a[fm][3])
                         : "r"(ad));
        }
        uint32_t b[4][4];
#pragma unroll
        for (int np = 0; np < 4; np++) {
            int krw = kb + ke + lr;
            uint32_t bn = (uint32_t)(warp_n + np * 16 + lh * 8) * 2;
            uint32_t bd = Bbase + krw * 256 + (bn ^ ((krw & 7) << 4));
            asm volatile("ldmatrix.sync.aligned.m8n8.x4.trans.shared.b16 {%0,%1,%2,%3}, [%4];"
                         : "=r"(b[np][0]), "=r"(b[np][1]), "=r"(b[np][2]), "=r"(b[np][3])
                         : "r"(bd));
        }
#pragma unroll
        for (int fm = 0; fm < 4; fm++)
#pragma unroll
            for (int fn = 0; fn < 8; fn++) {
                const int np = fn >> 1, pr = fn & 1;
                asm volatile(
                    "mma.sync.aligned.m16n8k16.row.col.f32.f16.f16.f32 "
                    "{%0,%1,%2,%3}, {%4,%5,%6,%7}, {%8,%9}, {%0,%1,%2,%3};"
                    : "+f"(acc[fm][fn][0]), "+f"(acc[fm][fn][1]),
                      "+f"(acc[fm][fn][2]), "+f"(acc[fm][fn][3])
                    : "r"(a[fm][0]), "r"(a[fm][1]), "r"(a[fm][2]), "r"(a[fm][3]),
                      "r"(b[np][pr * 2]), "r"(b[np][pr * 2 + 1]));
            }
    };

    // ---- prologue: W -> SW, X chunk 0 -> stage 0 ----
#pragma unroll
    for (int p = 0; p < 8; p++) {
        int u = tid + p * 256;
        int row = u >> 4, seg = u & 15;
        const float4* src = (const float4*)(W + row * NF + seg * 8);
        float4 v0 = src[0], v1 = src[1];
        uint4 w;
        w.x = packh2(v0.x, v0.y); w.y = packh2(v0.z, v0.w);
        w.z = packh2(v1.x, v1.y); w.w = packh2(v1.z, v1.w);
        sts16(SW + row * 256 + ((seg * 16) ^ ((row & 7) << 4)), w);
    }
    loadXw(0, 0); stsXw(0, 0);
    loadXw(0, 1); stsXw(0, 1);
    zero_acc();
    __syncthreads();                                    // barrier 1

    // ---- phase 1 chunk 0 (stage 0) + stage X chunk 1 -> stage 1 ----
    loadXw(1, 0);
    mma_step(0, 0, SW, 0);  mma_step(0, 1, SW, 0);
    stsXw(1, 0);
    loadXw(1, 1);
    mma_step(0, 2, SW, 0);  mma_step(0, 3, SW, 0);
    stsXw(1, 1);
    __syncthreads();                                    // barrier 2

    // ---- phase 1 chunk 1 (stage 1) + stage adj chunk 0 -> stage 0 ----
    loadAw(0, 0);
    mma_step(1, 0, SW, 64); mma_step(1, 1, SW, 64);
    stsAw(0, 0);
    loadAw(0, 1);
    mma_step(1, 2, SW, 64); mma_step(1, 3, SW, 64);
    stsAw(0, 1);

    // phase-1 epilogue: acc -> SXW (separate region; no barrier needed first)
#pragma unroll
    for (int fm = 0; fm < 4; fm++) {
        const int r0 = warp_m + fm * 16 + grp;
#pragma unroll
        for (int fn = 0; fn < 8; fn++) {
            const int cb = (warp_n + fn * 8 + tg * 2) * 2;
            uint32_t h0 = packh2(acc[fm][fn][0], acc[fm][fn][1]);
            uint32_t h1 = packh2(acc[fm][fn][2], acc[fm][fn][3]);
            asm volatile("st.shared.b32 [%0], %1;"
                         :: "r"(SXW + r0 * 256 + (cb ^ ((r0 & 7) << 4))), "r"(h0) : "memory");
            asm volatile("st.shared.b32 [%0], %1;"
                         :: "r"(SXW + (r0 + 8) * 256 + (cb ^ (((r0 + 8) & 7) << 4))), "r"(h1) : "memory");
        }
    }
    zero_acc();
    __syncthreads();                                    // barrier 3 (boundary)

    // ---- phase 2 chunk 0 (stage 0) + stage adj chunk 1 -> stage 1 ----
    loadAw(1, 0);
    mma_step(0, 0, SXW, 0);   mma_step(0, 1, SXW, 0);
    stsAw(1, 0);
    loadAw(1, 1);
    mma_step(0, 2, SXW, 0);   mma_step(0, 3, SXW, 0);
    stsAw(1, 1);
    __syncthreads();                                    // barrier 4

    // ---- phase 2 chunk 1 (stage 1) + adj chunk 2 -> stage 0 ----
    loadAw(2, 0);
    mma_step(1, 0, SXW, 64);  mma_step(1, 1, SXW, 64);
    stsAw(0, 0);
    loadAw(2, 1);
    mma_step(1, 2, SXW, 64);  mma_step(1, 3, SXW, 64);
    stsAw(0, 1);
    __syncthreads();                                    // barrier 5

    // ---- phase 2 chunk 2 (stage 0) + adj chunk 3 -> stage 1 ----
    loadAw(3, 0);
    mma_step(0, 0, SXW, 128); mma_step(0, 1, SXW, 128);
    stsAw(1, 0);
    loadAw(3, 1);
    mma_step(0, 2, SXW, 128); mma_step(0, 3, SXW, 128);
    stsAw(1, 1);
    __syncthreads();                                    // barrier 6

    // ---- phase 2 chunk 3 (stage 1) ----
    mma_step(1, 0, SXW, 192); mma_step(1, 1, SXW, 192);
    mma_step(1, 2, SXW, 192); mma_step(1, 3, SXW, 192);

    // phase-2 epilogue
#pragma unroll
    for (int fm = 0; fm < 4; fm++) {
        const int r0 = warp_m + fm * 16 + grp;
#pragma unroll
        for (int fn = 0; fn < 8; fn++) {
            const int col = warp_n + fn * 8 + tg * 2;
            float2 b2 = *(const float2*)(bias + col);
            float2 v0 = { acc[fm][fn][0] + b2.x, acc[fm][fn][1] + b2.y };
            float2 v1 = { acc[fm][fn][2] + b2.x, acc[fm][fn][3] + b2.y };
            *(float2*)(out + ((size_t)r0 * NT + t) * NF + col)       = v0;
            *(float2*)(out + ((size_t)(r0 + 8) * NT + t) * NF + col) = v1;
        }
    }
}

// ---------------------------------------------------------------------------
extern "C" void kernel_launch(void* const* d_in, const int* in_sizes, int n_in,
                              void* d_out, int out_size) {
    (void)in_sizes; (void)n_in; (void)out_size;
    const float* node_feats = (const float*)d_in[0];   // [256,2048,128]
    const float* adj        = (const float*)d_in[1];   // [256,256]
    const float* weight     = (const float*)d_in[2];   // [128,128]
    const float* bias       = (const float*)d_in[3];   // [128]
    float* out = (float*)d_out;

    cudaFuncSetAttribute(fused_gcn, cudaFuncAttributeMaxDynamicSharedMemorySize, SMEM_TOT);

    prep_kernel<<<NN, 256>>>(adj);
    fused_gcn<<<NT, 256, SMEM_TOT>>>(node_feats, weight, out, bias);
}